// round 1
// baseline (speedup 1.0000x reference)
#include <cuda_runtime.h>
#include <cuda_bf16.h>
#include <math.h>

// Problem constants
#define Bsz 8
#define Tseq 2048
#define FEAT 512
#define HID 512
#define SCALE 0.25f   // 1/sqrt(16)

// Scratch (device globals; allocation-free per harness rules)
__device__ float g_Q[(long)Bsz * Tseq * HID];          // 32 MB
__device__ float g_K[(long)Bsz * Tseq * HID];          // 32 MB
__device__ float g_V[(long)Bsz * Tseq * HID];          // 32 MB
__device__ float g_S[(long)Bsz * Tseq * Tseq];         // 128 MB

// ---------------------------------------------------------------------------
// SGEMM NN:  C[m,n] = alpha * sum_k A[m,k] * B[k,n]  (+ bias[n] if given)
// Block tile 128x128, K-step 8, 256 threads, 8x8 per-thread register tile.
// All dims assumed divisible by tile sizes (true for this problem).
// ---------------------------------------------------------------------------
#define BM 128
#define BN 128
#define BKK 8
#define TM 8
#define TN 8

__global__ __launch_bounds__(256, 2)
void sgemm_nn(const float* __restrict__ A, const float* __restrict__ B,
              const float* __restrict__ bias, float* __restrict__ C,
              int M, int N, int K,
              long sA, long sB, long sC, float alpha)
{
    A += (long)blockIdx.z * sA;
    B += (long)blockIdx.z * sB;
    C += (long)blockIdx.z * sC;

    __shared__ float As[BKK][BM];
    __shared__ float Bs[BKK][BN];

    const int tid = threadIdx.x;
    const int bm = blockIdx.y * BM;
    const int bn = blockIdx.x * BN;

    // A tile load: 128 rows x 8 cols, one float4 per thread
    const int arow = tid >> 1;           // 0..127
    const int acol = (tid & 1) * 4;      // 0 or 4
    // B tile load: 8 rows x 128 cols, one float4 per thread
    const int brow = tid >> 5;           // 0..7
    const int bcol = (tid & 31) * 4;     // 0..124

    const int tx = (tid & 15) * TN;      // 0..120
    const int ty = (tid >> 4) * TM;      // 0..120

    float acc[TM][TN];
    #pragma unroll
    for (int i = 0; i < TM; i++)
        #pragma unroll
        for (int j = 0; j < TN; j++)
            acc[i][j] = 0.0f;

    const float* Aptr = A + (long)bm * K;
    const float* Bptr = B + bn;

    for (int k0 = 0; k0 < K; k0 += BKK) {
        float4 av = *reinterpret_cast<const float4*>(Aptr + (long)arow * K + k0 + acol);
        As[acol + 0][arow] = av.x;
        As[acol + 1][arow] = av.y;
        As[acol + 2][arow] = av.z;
        As[acol + 3][arow] = av.w;

        float4 bv = *reinterpret_cast<const float4*>(Bptr + (long)(k0 + brow) * N + bcol);
        *reinterpret_cast<float4*>(&Bs[brow][bcol]) = bv;

        __syncthreads();

        #pragma unroll
        for (int kk = 0; kk < BKK; kk++) {
            float a[TM], b[TN];
            #pragma unroll
            for (int i = 0; i < TM; i += 4) {
                float4 t = *reinterpret_cast<const float4*>(&As[kk][ty + i]);
                a[i + 0] = t.x; a[i + 1] = t.y; a[i + 2] = t.z; a[i + 3] = t.w;
            }
            #pragma unroll
            for (int j = 0; j < TN; j += 4) {
                float4 t = *reinterpret_cast<const float4*>(&Bs[kk][tx + j]);
                b[j + 0] = t.x; b[j + 1] = t.y; b[j + 2] = t.z; b[j + 3] = t.w;
            }
            #pragma unroll
            for (int i = 0; i < TM; i++)
                #pragma unroll
                for (int j = 0; j < TN; j++)
                    acc[i][j] = fmaf(a[i], b[j], acc[i][j]);
        }
        __syncthreads();
    }

    #pragma unroll
    for (int i = 0; i < TM; i++) {
        long crow = (long)(bm + ty + i) * N + bn;
        #pragma unroll
        for (int j = 0; j < TN; j += 4) {
            float4 o;
            o.x = acc[i][j + 0] * alpha;
            o.y = acc[i][j + 1] * alpha;
            o.z = acc[i][j + 2] * alpha;
            o.w = acc[i][j + 3] * alpha;
            if (bias) {
                o.x += bias[bn + tx + j + 0];
                o.y += bias[bn + tx + j + 1];
                o.z += bias[bn + tx + j + 2];
                o.w += bias[bn + tx + j + 3];
            }
            *reinterpret_cast<float4*>(C + crow + tx + j) = o;
        }
    }
}

// ---------------------------------------------------------------------------
// SGEMM NT:  C[m,n] = alpha * sum_k A[m,k] * B[n,k]
// A: [M,K] row-major, B: [N,K] row-major (both K-contiguous)
// ---------------------------------------------------------------------------
__global__ __launch_bounds__(256, 2)
void sgemm_nt(const float* __restrict__ A, const float* __restrict__ B,
              float* __restrict__ C,
              int M, int N, int K,
              long sA, long sB, long sC, float alpha)
{
    A += (long)blockIdx.z * sA;
    B += (long)blockIdx.z * sB;
    C += (long)blockIdx.z * sC;

    __shared__ float As[BKK][BM];
    __shared__ float Bs[BKK][BN];

    const int tid = threadIdx.x;
    const int bm = blockIdx.y * BM;
    const int bn = blockIdx.x * BN;

    const int arow = tid >> 1;
    const int acol = (tid & 1) * 4;

    const int tx = (tid & 15) * TN;
    const int ty = (tid >> 4) * TM;

    float acc[TM][TN];
    #pragma unroll
    for (int i = 0; i < TM; i++)
        #pragma unroll
        for (int j = 0; j < TN; j++)
            acc[i][j] = 0.0f;

    const float* Aptr = A + (long)bm * K;
    const float* Bptr = B + (long)bn * K;

    for (int k0 = 0; k0 < K; k0 += BKK) {
        float4 av = *reinterpret_cast<const float4*>(Aptr + (long)arow * K + k0 + acol);
        As[acol + 0][arow] = av.x;
        As[acol + 1][arow] = av.y;
        As[acol + 2][arow] = av.z;
        As[acol + 3][arow] = av.w;

        float4 bv = *reinterpret_cast<const float4*>(Bptr + (long)arow * K + k0 + acol);
        Bs[acol + 0][arow] = bv.x;
        Bs[acol + 1][arow] = bv.y;
        Bs[acol + 2][arow] = bv.z;
        Bs[acol + 3][arow] = bv.w;

        __syncthreads();

        #pragma unroll
        for (int kk = 0; kk < BKK; kk++) {
            float a[TM], b[TN];
            #pragma unroll
            for (int i = 0; i < TM; i += 4) {
                float4 t = *reinterpret_cast<const float4*>(&As[kk][ty + i]);
                a[i + 0] = t.x; a[i + 1] = t.y; a[i + 2] = t.z; a[i + 3] = t.w;
            }
            #pragma unroll
            for (int j = 0; j < TN; j += 4) {
                float4 t = *reinterpret_cast<const float4*>(&Bs[kk][tx + j]);
                b[j + 0] = t.x; b[j + 1] = t.y; b[j + 2] = t.z; b[j + 3] = t.w;
            }
            #pragma unroll
            for (int i = 0; i < TM; i++)
                #pragma unroll
                for (int j = 0; j < TN; j++)
                    acc[i][j] = fmaf(a[i], b[j], acc[i][j]);
        }
        __syncthreads();
    }

    #pragma unroll
    for (int i = 0; i < TM; i++) {
        long crow = (long)(bm + ty + i) * N + bn;
        #pragma unroll
        for (int j = 0; j < TN; j += 4) {
            float4 o;
            o.x = acc[i][j + 0] * alpha;
            o.y = acc[i][j + 1] * alpha;
            o.z = acc[i][j + 2] * alpha;
            o.w = acc[i][j + 3] * alpha;
            *reinterpret_cast<float4*>(C + crow + tx + j) = o;
        }
    }
}

// ---------------------------------------------------------------------------
// Row softmax over rows of length 2048. One block (256 threads) per row.
// ---------------------------------------------------------------------------
__global__ __launch_bounds__(256)
void softmax_rows(float* __restrict__ S)
{
    float* p = S + (long)blockIdx.x * Tseq;
    const int tid = threadIdx.x;

    float v[8];
    float m = -1e30f;
    #pragma unroll
    for (int i = 0; i < 8; i++) {
        v[i] = p[i * 256 + tid];
        m = fmaxf(m, v[i]);
    }

    __shared__ float red[8];
    #pragma unroll
    for (int o = 16; o > 0; o >>= 1)
        m = fmaxf(m, __shfl_xor_sync(0xffffffffu, m, o));
    if ((tid & 31) == 0) red[tid >> 5] = m;
    __syncthreads();
    float mb = red[0];
    #pragma unroll
    for (int i = 1; i < 8; i++) mb = fmaxf(mb, red[i]);
    __syncthreads();  // allow re-use of red[]

    float s = 0.0f;
    #pragma unroll
    for (int i = 0; i < 8; i++) {
        v[i] = expf(v[i] - mb);
        s += v[i];
    }
    #pragma unroll
    for (int o = 16; o > 0; o >>= 1)
        s += __shfl_xor_sync(0xffffffffu, s, o);
    if ((tid & 31) == 0) red[tid >> 5] = s;
    __syncthreads();
    float tot = 0.0f;
    #pragma unroll
    for (int i = 0; i < 8; i++) tot += red[i];

    float inv = 1.0f / tot;
    #pragma unroll
    for (int i = 0; i < 8; i++)
        p[i * 256 + tid] = v[i] * inv;
}

// ---------------------------------------------------------------------------
// Launch
// ---------------------------------------------------------------------------
extern "C" void kernel_launch(void* const* d_in, const int* in_sizes, int n_in,
                              void* d_out, int out_size)
{
    const float* q  = (const float*)d_in[0];
    const float* k  = (const float*)d_in[1];
    const float* v  = (const float*)d_in[2];
    const float* Wq = (const float*)d_in[3];
    const float* bq = (const float*)d_in[4];
    const float* Wk = (const float*)d_in[5];
    const float* bk = (const float*)d_in[6];
    const float* Wv = (const float*)d_in[7];
    const float* bv = (const float*)d_in[8];
    float* out = (float*)d_out;

    float *gQ, *gK, *gV, *gS;
    cudaGetSymbolAddress((void**)&gQ, g_Q);
    cudaGetSymbolAddress((void**)&gK, g_K);
    cudaGetSymbolAddress((void**)&gV, g_V);
    cudaGetSymbolAddress((void**)&gS, g_S);

    const int Mrows = Bsz * Tseq;  // 16384

    // 1) Projections: [16384,512] = [16384,512] @ [512,512] + bias
    dim3 gp(HID / BN, Mrows / BM, 1);
    sgemm_nn<<<gp, 256>>>(q, Wq, bq, gQ, Mrows, HID, FEAT, 0, 0, 0, 1.0f);
    sgemm_nn<<<gp, 256>>>(k, Wk, bk, gK, Mrows, HID, FEAT, 0, 0, 0, 1.0f);
    sgemm_nn<<<gp, 256>>>(v, Wv, bv, gV, Mrows, HID, FEAT, 0, 0, 0, 1.0f);

    // 2) Energy: per batch S = 0.25 * Q @ K^T   (2048 x 2048 x 512)
    dim3 ge(Tseq / BN, Tseq / BM, Bsz);
    sgemm_nt<<<ge, 256>>>(gQ, gK, gS, Tseq, Tseq, HID,
                          (long)Tseq * HID, (long)Tseq * HID,
                          (long)Tseq * Tseq, SCALE);

    // 3) Softmax over last dim
    softmax_rows<<<Bsz * Tseq, 256>>>(gS);

    // 4) Output: per batch out = P @ V  (2048 x 512 x 2048)
    dim3 go(HID / BN, Tseq / BM, Bsz);
    sgemm_nn<<<go, 256>>>(gS, gV, nullptr, out, Tseq, HID, Tseq,
                          (long)Tseq * Tseq, (long)Tseq * HID,
                          (long)Tseq * HID, 1.0f);
}

// round 4
// speedup vs baseline: 2.4241x; 2.4241x over previous
#include <cuda_runtime.h>
#include <cuda_bf16.h>
#include <stdint.h>

typedef __nv_bfloat16 bf16;

#define BZ 8
#define TT 2048
#define FT 512
#define HD 512
#define MTOT (BZ * TT)   // 16384

// ---------------- scratch (device globals; allocation-free) ----------------
__device__ __align__(16) bf16 g_qh[MTOT * FT], g_ql[MTOT * FT];
__device__ __align__(16) bf16 g_kh[MTOT * FT], g_kl[MTOT * FT];
__device__ __align__(16) bf16 g_vh[MTOT * FT], g_vl[MTOT * FT];
__device__ __align__(16) bf16 g_Wqh[FT * HD], g_Wql[FT * HD];
__device__ __align__(16) bf16 g_Wkh[FT * HD], g_Wkl[FT * HD];
__device__ __align__(16) bf16 g_Wvh[FT * HD], g_Wvl[FT * HD];
__device__ __align__(16) bf16 g_Qh[MTOT * HD], g_Ql[MTOT * HD];
__device__ __align__(16) bf16 g_Kh[MTOT * HD], g_Kl[MTOT * HD];
__device__ __align__(16) bf16 g_Vh[MTOT * HD], g_Vl[MTOT * HD];
__device__ __align__(16) bf16 g_Vth[(size_t)BZ * HD * TT], g_Vtl[(size_t)BZ * HD * TT];
__device__ __align__(16) float g_S[(size_t)BZ * TT * TT];
__device__ __align__(16) bf16 g_Ph[(size_t)BZ * TT * TT], g_Pl[(size_t)BZ * TT * TT];

// ---------------- helpers ----------------
__device__ __forceinline__ uint32_t smem_u32(const void* p) {
    uint32_t a;
    asm("{ .reg .u64 t; cvta.to.shared.u64 t, %1; cvt.u32.u64 %0, t; }" : "=r"(a) : "l"(p));
    return a;
}

#define CP16(dst, src) \
    asm volatile("cp.async.cg.shared.global [%0], [%1], 16;" :: "r"(dst), "l"(src) : "memory")

#define LDSM4(r, addr) \
    asm volatile("ldmatrix.sync.aligned.m8n8.x4.shared.b16 {%0,%1,%2,%3}, [%4];" \
                 : "=r"((r)[0]), "=r"((r)[1]), "=r"((r)[2]), "=r"((r)[3]) : "r"(addr))

#define MMA16816(d, a, b0, b1) \
    asm volatile("mma.sync.aligned.m16n8k16.row.col.f32.bf16.bf16.f32 " \
                 "{%0,%1,%2,%3}, {%4,%5,%6,%7}, {%8,%9}, {%0,%1,%2,%3};" \
                 : "+f"((d)[0]), "+f"((d)[1]), "+f"((d)[2]), "+f"((d)[3]) \
                 : "r"((a)[0]), "r"((a)[1]), "r"((a)[2]), "r"((a)[3]), "r"(b0), "r"(b1))

// ---------------- warp-MMA GEMM ----------------
// D[m,n] = sum_k A[m,k]*B[n,k], split-bf16 3-term: Ah*Bh + Ah*Bl + Al*Bh
// MODE 0: out = (acc + bias[n]) * scale -> bf16 hi/lo row-major
// MODE 1: out = acc -> fp32 row-major (batched via blockIdx.z)
static constexpr int TILE_B = 16384;            // 128 rows x 128 bytes
static constexpr int STAGE_B = 4 * TILE_B;      // Ah, Al, Bh, Bl
static constexpr int GEMM_SMEM = 2 * STAGE_B;   // double buffer = 128 KB

__device__ __forceinline__ void load_tile(uint32_t dstbase, const bf16* src, int ld, int tid)
{
    #pragma unroll
    for (int j = 0; j < 4; j++) {
        const int seg = tid + j * 256;
        const int row = seg >> 3;
        const int colb = (seg & 7) * 16;
        const uint32_t off = (uint32_t)(row * 128 + colb);
        const uint32_t sw = off ^ ((off >> 3) & 0x70);
        CP16(dstbase + sw, (const char*)src + (long)row * ld * 2 + colb);
    }
}

template <int MODE>
__global__ __launch_bounds__(256, 1)
void gemm_mma(const bf16* __restrict__ Ah, const bf16* __restrict__ Al,
              const bf16* __restrict__ Bh, const bf16* __restrict__ Bl,
              int lda, int ldb, long sA, long sB, int K,
              const float* __restrict__ bias, float scale,
              float* __restrict__ outF, bf16* __restrict__ outH, bf16* __restrict__ outL,
              int ldo, long sO)
{
    extern __shared__ char smem[];
    const uint32_t sbase = smem_u32(smem);
    const int tid = threadIdx.x;
    const int wid = tid >> 5;
    const int L = tid & 31;
    const int bm = blockIdx.y * 128;
    const int bn = blockIdx.x * 128;
    const int wm = wid & 1;       // 0..1  (64 rows each)
    const int wn = wid >> 1;      // 0..3  (32 cols each)

    const bf16* pAh = Ah + (long)blockIdx.z * sA + (long)bm * lda;
    const bf16* pAl = Al + (long)blockIdx.z * sA + (long)bm * lda;
    const bf16* pBh = Bh + (long)blockIdx.z * sB + (long)bn * ldb;
    const bf16* pBl = Bl + (long)blockIdx.z * sB + (long)bn * ldb;

    // ldmatrix lane offsets: keep UNSWIZZLED base; swizzle pattern depends only
    // on row bits (invariant under +kk*32 column advance, which never carries).
    const int lr = L & 15;
    const int lc = (L >> 4) * 16;
    uint32_t aoffu[4], apat[4], boffu[2], bpat[2];
    #pragma unroll
    for (int mt = 0; mt < 4; mt++) {
        const uint32_t off = (uint32_t)((wm * 64 + mt * 16 + lr) * 128 + lc);
        aoffu[mt] = off;
        apat[mt] = (off >> 3) & 0x70;
    }
    #pragma unroll
    for (int ng = 0; ng < 2; ng++) {
        const uint32_t off = (uint32_t)((wn * 32 + ng * 16 + lr) * 128 + lc);
        boffu[ng] = off;
        bpat[ng] = (off >> 3) & 0x70;
    }

    float acc[4][4][4];
    #pragma unroll
    for (int mt = 0; mt < 4; mt++)
        #pragma unroll
        for (int nt = 0; nt < 4; nt++)
            #pragma unroll
            for (int r = 0; r < 4; r++)
                acc[mt][nt][r] = 0.0f;

    const int nchunk = K / 64;

    // prologue: stage 0
    load_tile(sbase + 0 * TILE_B, pAh, lda, tid);
    load_tile(sbase + 1 * TILE_B, pAl, lda, tid);
    load_tile(sbase + 2 * TILE_B, pBh, ldb, tid);
    load_tile(sbase + 3 * TILE_B, pBl, ldb, tid);
    asm volatile("cp.async.commit_group;" ::: "memory");

    for (int ck = 0; ck < nchunk; ck++) {
        const int buf = ck & 1;
        if (ck + 1 < nchunk) {
            const int k0 = (ck + 1) * 64;
            const uint32_t db = sbase + (buf ^ 1) * STAGE_B;
            load_tile(db + 0 * TILE_B, pAh + k0, lda, tid);
            load_tile(db + 1 * TILE_B, pAl + k0, lda, tid);
            load_tile(db + 2 * TILE_B, pBh + k0, ldb, tid);
            load_tile(db + 3 * TILE_B, pBl + k0, ldb, tid);
            asm volatile("cp.async.commit_group;" ::: "memory");
            asm volatile("cp.async.wait_group 1;" ::: "memory");
        } else {
            asm volatile("cp.async.wait_group 0;" ::: "memory");
        }
        __syncthreads();

        const uint32_t cb = sbase + buf * STAGE_B;
        #pragma unroll
        for (int kk = 0; kk < 4; kk++) {
            uint32_t ah[4][4], al[4][4], bh[2][4], bl[2][4];
            #pragma unroll
            for (int mt = 0; mt < 4; mt++) {
                const uint32_t sw = (aoffu[mt] + kk * 32) ^ apat[mt];
                LDSM4(ah[mt], cb + 0 * TILE_B + sw);
                LDSM4(al[mt], cb + 1 * TILE_B + sw);
            }
            #pragma unroll
            for (int ng = 0; ng < 2; ng++) {
                const uint32_t sw = (boffu[ng] + kk * 32) ^ bpat[ng];
                LDSM4(bh[ng], cb + 2 * TILE_B + sw);
                LDSM4(bl[ng], cb + 3 * TILE_B + sw);
            }
            #pragma unroll
            for (int mt = 0; mt < 4; mt++) {
                #pragma unroll
                for (int nt = 0; nt < 4; nt++) {
                    const uint32_t bh0 = bh[nt >> 1][nt & 1];
                    const uint32_t bh1 = bh[nt >> 1][(nt & 1) + 2];
                    const uint32_t bl0 = bl[nt >> 1][nt & 1];
                    const uint32_t bl1 = bl[nt >> 1][(nt & 1) + 2];
                    MMA16816(acc[mt][nt], ah[mt], bh0, bh1);
                    MMA16816(acc[mt][nt], ah[mt], bl0, bl1);
                    MMA16816(acc[mt][nt], al[mt], bh0, bh1);
                }
            }
        }
        __syncthreads();
    }

    // epilogue
    const int r0 = bm + wm * 64 + (L >> 2);
    const int c0 = bn + wn * 32 + (L & 3) * 2;
    #pragma unroll
    for (int mt = 0; mt < 4; mt++) {
        #pragma unroll
        for (int nt = 0; nt < 4; nt++) {
            const int row = r0 + mt * 16;
            const int col = c0 + nt * 8;
            if (MODE == 1) {
                float* po = outF + (size_t)blockIdx.z * sO;
                float2 v0 = make_float2(acc[mt][nt][0], acc[mt][nt][1]);
                float2 v1 = make_float2(acc[mt][nt][2], acc[mt][nt][3]);
                *reinterpret_cast<float2*>(po + (size_t)row * ldo + col) = v0;
                *reinterpret_cast<float2*>(po + (size_t)(row + 8) * ldo + col) = v1;
            } else {
                const float b0 = bias[col], b1 = bias[col + 1];
                float x0 = (acc[mt][nt][0] + b0) * scale;
                float x1 = (acc[mt][nt][1] + b1) * scale;
                float x2 = (acc[mt][nt][2] + b0) * scale;
                float x3 = (acc[mt][nt][3] + b1) * scale;
                bf16 h0 = __float2bfloat16(x0), h1 = __float2bfloat16(x1);
                bf16 h2 = __float2bfloat16(x2), h3 = __float2bfloat16(x3);
                bf16 l0 = __float2bfloat16(x0 - __bfloat162float(h0));
                bf16 l1 = __float2bfloat16(x1 - __bfloat162float(h1));
                bf16 l2 = __float2bfloat16(x2 - __bfloat162float(h2));
                bf16 l3 = __float2bfloat16(x3 - __bfloat162float(h3));
                __nv_bfloat162 hh0; hh0.x = h0; hh0.y = h1;
                __nv_bfloat162 hh1; hh1.x = h2; hh1.y = h3;
                __nv_bfloat162 ll0; ll0.x = l0; ll0.y = l1;
                __nv_bfloat162 ll1; ll1.x = l2; ll1.y = l3;
                *reinterpret_cast<__nv_bfloat162*>(outH + (size_t)row * ldo + col) = hh0;
                *reinterpret_cast<__nv_bfloat162*>(outH + (size_t)(row + 8) * ldo + col) = hh1;
                *reinterpret_cast<__nv_bfloat162*>(outL + (size_t)row * ldo + col) = ll0;
                *reinterpret_cast<__nv_bfloat162*>(outL + (size_t)(row + 8) * ldo + col) = ll1;
            }
        }
    }
}

// ---------------- small kernels ----------------
__global__ __launch_bounds__(256) void fsplit(const float* __restrict__ x,
                                              bf16* __restrict__ h, bf16* __restrict__ l)
{
    const int i = (blockIdx.x * 256 + threadIdx.x) * 4;
    float4 v = *reinterpret_cast<const float4*>(x + i);
    bf16 h0 = __float2bfloat16(v.x), h1 = __float2bfloat16(v.y);
    bf16 h2 = __float2bfloat16(v.z), h3 = __float2bfloat16(v.w);
    bf16 l0 = __float2bfloat16(v.x - __bfloat162float(h0));
    bf16 l1 = __float2bfloat16(v.y - __bfloat162float(h1));
    bf16 l2 = __float2bfloat16(v.z - __bfloat162float(h2));
    bf16 l3 = __float2bfloat16(v.w - __bfloat162float(h3));
    __nv_bfloat162 a, b;
    a.x = h0; a.y = h1; b.x = h2; b.y = h3;
    *reinterpret_cast<__nv_bfloat162*>(h + i) = a;
    *reinterpret_cast<__nv_bfloat162*>(h + i + 2) = b;
    a.x = l0; a.y = l1; b.x = l2; b.y = l3;
    *reinterpret_cast<__nv_bfloat162*>(l + i) = a;
    *reinterpret_cast<__nv_bfloat162*>(l + i + 2) = b;
}

// W [K=512, N=512] -> Wt hi/lo [N, K]
__global__ __launch_bounds__(256) void wsplit(const float* __restrict__ W,
                                              bf16* __restrict__ Wth, bf16* __restrict__ Wtl)
{
    __shared__ float t[32][33];
    const int n0 = blockIdx.x * 32, k0 = blockIdx.y * 32;
    const int tx = threadIdx.x & 31, ty = threadIdx.x >> 5;
    #pragma unroll
    for (int i = 0; i < 4; i++) {
        const int r = ty + i * 8;
        t[r][tx] = W[(size_t)(k0 + r) * HD + n0 + tx];
    }
    __syncthreads();
    #pragma unroll
    for (int i = 0; i < 4; i++) {
        const int r = ty + i * 8;          // n
        const float v = t[tx][r];
        bf16 h = __float2bfloat16(v);
        bf16 l = __float2bfloat16(v - __bfloat162float(h));
        const size_t dst = (size_t)(n0 + r) * FT + k0 + tx;
        Wth[dst] = h;
        Wtl[dst] = l;
    }
}

// V hi/lo [B*T, H] -> Vt hi/lo [B][H][T]
__global__ __launch_bounds__(256) void transpose_v(const bf16* __restrict__ Vh,
                                                   const bf16* __restrict__ Vl,
                                                   bf16* __restrict__ Vth, bf16* __restrict__ Vtl)
{
    __shared__ bf16 th[32][33], tl[32][33];
    const int b = blockIdx.z;
    const int h0 = blockIdx.x * 32, s0 = blockIdx.y * 32;
    const int tx = threadIdx.x & 31, ty = threadIdx.x >> 5;
    #pragma unroll
    for (int i = 0; i < 4; i++) {
        const int r = ty + i * 8;
        const size_t src = ((size_t)b * TT + s0 + r) * HD + h0 + tx;
        th[r][tx] = Vh[src];
        tl[r][tx] = Vl[src];
    }
    __syncthreads();
    #pragma unroll
    for (int i = 0; i < 4; i++) {
        const int r = ty + i * 8;          // h
        const size_t dst = ((size_t)b * HD + h0 + r) * TT + s0 + tx;
        Vth[dst] = th[tx][r];
        Vtl[dst] = tl[tx][r];
    }
}

// softmax over rows of 2048; writes P as bf16 hi/lo
__global__ __launch_bounds__(256) void softmax_k(const float* __restrict__ S,
                                                 bf16* __restrict__ Ph, bf16* __restrict__ Pl)
{
    const size_t off = (size_t)blockIdx.x * TT;
    const int tid = threadIdx.x;
    const float* p = S + off + tid * 8;
    float v[8];
    float4 a = *reinterpret_cast<const float4*>(p);
    float4 b = *reinterpret_cast<const float4*>(p + 4);
    v[0] = a.x; v[1] = a.y; v[2] = a.z; v[3] = a.w;
    v[4] = b.x; v[5] = b.y; v[6] = b.z; v[7] = b.w;

    __shared__ float red[8];
    float m = v[0];
    #pragma unroll
    for (int i = 1; i < 8; i++) m = fmaxf(m, v[i]);
    #pragma unroll
    for (int o = 16; o > 0; o >>= 1) m = fmaxf(m, __shfl_xor_sync(0xffffffffu, m, o));
    if ((tid & 31) == 0) red[tid >> 5] = m;
    __syncthreads();
    float M = red[0];
    #pragma unroll
    for (int i = 1; i < 8; i++) M = fmaxf(M, red[i]);
    __syncthreads();

    float s = 0.f;
    #pragma unroll
    for (int i = 0; i < 8; i++) { v[i] = __expf(v[i] - M); s += v[i]; }
    #pragma unroll
    for (int o = 16; o > 0; o >>= 1) s += __shfl_xor_sync(0xffffffffu, s, o);
    if ((tid & 31) == 0) red[tid >> 5] = s;
    __syncthreads();
    float tot = 0.f;
    #pragma unroll
    for (int i = 0; i < 8; i++) tot += red[i];
    const float inv = __fdividef(1.0f, tot);

    bf16* ph = Ph + off + tid * 8;
    bf16* pl = Pl + off + tid * 8;
    #pragma unroll
    for (int i = 0; i < 8; i += 2) {
        float x0 = v[i] * inv, x1 = v[i + 1] * inv;
        bf16 h0 = __float2bfloat16(x0), h1 = __float2bfloat16(x1);
        bf16 l0 = __float2bfloat16(x0 - __bfloat162float(h0));
        bf16 l1 = __float2bfloat16(x1 - __bfloat162float(h1));
        __nv_bfloat162 hh; hh.x = h0; hh.y = h1;
        __nv_bfloat162 ll; ll.x = l0; ll.y = l1;
        *reinterpret_cast<__nv_bfloat162*>(ph + i) = hh;
        *reinterpret_cast<__nv_bfloat162*>(pl + i) = ll;
    }
}

// ---------------- launch ----------------
extern "C" void kernel_launch(void* const* d_in, const int* in_sizes, int n_in,
                              void* d_out, int out_size)
{
    const float* q  = (const float*)d_in[0];
    const float* k  = (const float*)d_in[1];
    const float* v  = (const float*)d_in[2];
    const float* Wq = (const float*)d_in[3];
    const float* bq = (const float*)d_in[4];
    const float* Wk = (const float*)d_in[5];
    const float* bk = (const float*)d_in[6];
    const float* Wv = (const float*)d_in[7];
    const float* bv = (const float*)d_in[8];
    float* out = (float*)d_out;

    bf16 *qh, *ql, *kh, *kl, *vh, *vl;
    bf16 *wqh, *wql, *wkh, *wkl, *wvh, *wvl;
    bf16 *Qh, *Ql, *Kh, *Kl, *Vh, *Vl, *Vth, *Vtl, *Ph, *Pl;
    float* S;
    cudaGetSymbolAddress((void**)&qh, g_qh);   cudaGetSymbolAddress((void**)&ql, g_ql);
    cudaGetSymbolAddress((void**)&kh, g_kh);   cudaGetSymbolAddress((void**)&kl, g_kl);
    cudaGetSymbolAddress((void**)&vh, g_vh);   cudaGetSymbolAddress((void**)&vl, g_vl);
    cudaGetSymbolAddress((void**)&wqh, g_Wqh); cudaGetSymbolAddress((void**)&wql, g_Wql);
    cudaGetSymbolAddress((void**)&wkh, g_Wkh); cudaGetSymbolAddress((void**)&wkl, g_Wkl);
    cudaGetSymbolAddress((void**)&wvh, g_Wvh); cudaGetSymbolAddress((void**)&wvl, g_Wvl);
    cudaGetSymbolAddress((void**)&Qh, g_Qh);   cudaGetSymbolAddress((void**)&Ql, g_Ql);
    cudaGetSymbolAddress((void**)&Kh, g_Kh);   cudaGetSymbolAddress((void**)&Kl, g_Kl);
    cudaGetSymbolAddress((void**)&Vh, g_Vh);   cudaGetSymbolAddress((void**)&Vl, g_Vl);
    cudaGetSymbolAddress((void**)&Vth, g_Vth); cudaGetSymbolAddress((void**)&Vtl, g_Vtl);
    cudaGetSymbolAddress((void**)&S, g_S);
    cudaGetSymbolAddress((void**)&Ph, g_Ph);   cudaGetSymbolAddress((void**)&Pl, g_Pl);

    cudaFuncSetAttribute(gemm_mma<0>, cudaFuncAttributeMaxDynamicSharedMemorySize, GEMM_SMEM);
    cudaFuncSetAttribute(gemm_mma<1>, cudaFuncAttributeMaxDynamicSharedMemorySize, GEMM_SMEM);

    // 1) split inputs
    fsplit<<<MTOT * FT / 1024, 256>>>(q, qh, ql);
    fsplit<<<MTOT * FT / 1024, 256>>>(k, kh, kl);
    fsplit<<<MTOT * FT / 1024, 256>>>(v, vh, vl);
    // 2) transpose+split weights
    wsplit<<<dim3(16, 16), 256>>>(Wq, wqh, wql);
    wsplit<<<dim3(16, 16), 256>>>(Wk, wkh, wkl);
    wsplit<<<dim3(16, 16), 256>>>(Wv, wvh, wvl);
    // 3) projections (scale 0.25 folded into Q)
    dim3 gp(HD / 128, MTOT / 128, 1);
    gemm_mma<0><<<gp, 256, GEMM_SMEM>>>(qh, ql, wqh, wql, FT, FT, 0, 0, FT,
                                        bq, 0.25f, nullptr, Qh, Ql, HD, 0);
    gemm_mma<0><<<gp, 256, GEMM_SMEM>>>(kh, kl, wkh, wkl, FT, FT, 0, 0, FT,
                                        bk, 1.0f, nullptr, Kh, Kl, HD, 0);
    gemm_mma<0><<<gp, 256, GEMM_SMEM>>>(vh, vl, wvh, wvl, FT, FT, 0, 0, FT,
                                        bv, 1.0f, nullptr, Vh, Vl, HD, 0);
    // 4) transpose V
    transpose_v<<<dim3(HD / 32, TT / 32, BZ), 256>>>(Vh, Vl, Vth, Vtl);
    // 5) energy S = (0.25 Q) K^T
    dim3 ge(TT / 128, TT / 128, BZ);
    gemm_mma<1><<<ge, 256, GEMM_SMEM>>>(Qh, Ql, Kh, Kl, HD, HD,
                                        (long)TT * HD, (long)TT * HD, HD,
                                        nullptr, 1.0f, S, nullptr, nullptr,
                                        TT, (long)TT * TT);
    // 6) softmax -> P hi/lo
    softmax_k<<<MTOT, 256>>>(S, Ph, Pl);
    // 7) out = P V
    dim3 go(HD / 128, TT / 128, BZ);
    gemm_mma<1><<<go, 256, GEMM_SMEM>>>(Ph, Pl, Vth, Vtl, TT, TT,
                                        (long)TT * TT, (long)HD * TT, TT,
                                        nullptr, 1.0f, out, nullptr, nullptr,
                                        HD, (long)TT * HD);
}

// round 5
// speedup vs baseline: 2.4967x; 1.0300x over previous
#include <cuda_runtime.h>
#include <cuda_bf16.h>
#include <stdint.h>

typedef __nv_bfloat16 bf16;

#define BZ 8
#define TT 2048
#define FT 512
#define HD 512
#define MTOT (BZ * TT)   // 16384

// ---------------- scratch (device globals; allocation-free) ----------------
__device__ __align__(16) bf16 g_qh[MTOT * FT], g_ql[MTOT * FT];
__device__ __align__(16) bf16 g_kh[MTOT * FT], g_kl[MTOT * FT];
__device__ __align__(16) bf16 g_vh[MTOT * FT], g_vl[MTOT * FT];
__device__ __align__(16) bf16 g_Wqh[FT * HD], g_Wql[FT * HD];
__device__ __align__(16) bf16 g_Wkh[FT * HD], g_Wkl[FT * HD];
__device__ __align__(16) bf16 g_Wvh[FT * HD], g_Wvl[FT * HD];
__device__ __align__(16) bf16 g_Qh[MTOT * HD], g_Ql[MTOT * HD];
__device__ __align__(16) bf16 g_Kh[MTOT * HD], g_Kl[MTOT * HD];
__device__ __align__(16) bf16 g_Vh[MTOT * HD], g_Vl[MTOT * HD];
__device__ __align__(16) bf16 g_Vth[(size_t)BZ * HD * TT], g_Vtl[(size_t)BZ * HD * TT];
__device__ __align__(16) float g_S[(size_t)BZ * TT * TT];
__device__ __align__(16) bf16 g_Ph[(size_t)BZ * TT * TT], g_Pl[(size_t)BZ * TT * TT];

// ---------------- helpers ----------------
__device__ __forceinline__ uint32_t smem_u32(const void* p) {
    uint32_t a;
    asm("{ .reg .u64 t; cvta.to.shared.u64 t, %1; cvt.u32.u64 %0, t; }" : "=r"(a) : "l"(p));
    return a;
}

#define CP16(dst, src) \
    asm volatile("cp.async.cg.shared.global [%0], [%1], 16;" :: "r"(dst), "l"(src) : "memory")

#define LDSM4(r, addr) \
    asm volatile("ldmatrix.sync.aligned.m8n8.x4.shared.b16 {%0,%1,%2,%3}, [%4];" \
                 : "=r"((r)[0]), "=r"((r)[1]), "=r"((r)[2]), "=r"((r)[3]) : "r"(addr))

#define MMA16816(d, a, b0, b1) \
    asm volatile("mma.sync.aligned.m16n8k16.row.col.f32.bf16.bf16.f32 " \
                 "{%0,%1,%2,%3}, {%4,%5,%6,%7}, {%8,%9}, {%0,%1,%2,%3};" \
                 : "+f"((d)[0]), "+f"((d)[1]), "+f"((d)[2]), "+f"((d)[3]) \
                 : "r"((a)[0]), "r"((a)[1]), "r"((a)[2]), "r"((a)[3]), "r"(b0), "r"(b1))

// ---------------- warp-MMA GEMM ----------------
// D[m,n] = sum_k A[m,k]*B[n,k], split-bf16 3-term: Ah*Bh + Ah*Bl + Al*Bh
// K-chunk 32 (64B rows, SW64 swizzle), double-buffered, 64KB smem, 2 CTAs/SM.
static constexpr int TILE_B = 8192;             // 128 rows x 64 bytes
static constexpr int STAGE_B = 4 * TILE_B;      // Ah, Al, Bh, Bl = 32 KB
static constexpr int GEMM_SMEM = 2 * STAGE_B;   // 64 KB

__device__ __forceinline__ void load_tile(uint32_t dstbase, const bf16* src, int ld, int tid)
{
    #pragma unroll
    for (int j = 0; j < 2; j++) {
        const int seg = tid + j * 256;          // 512 segs of 16B
        const int row = seg >> 2;               // 0..127
        const int colb = (seg & 3) * 16;        // 0..48
        const uint32_t off = (uint32_t)(row * 64 + colb);
        const uint32_t sw = off ^ ((off >> 3) & 0x30);
        CP16(dstbase + sw, (const char*)src + (long)row * ld * 2 + colb);
    }
}

template <int MODE>
__global__ __launch_bounds__(256, 2)
void gemm_mma(const bf16* __restrict__ Ah, const bf16* __restrict__ Al,
              const bf16* __restrict__ Bh, const bf16* __restrict__ Bl,
              int lda, int ldb, long sA, long sB, int K,
              const float* __restrict__ bias, float scale,
              float* __restrict__ outF, bf16* __restrict__ outH, bf16* __restrict__ outL,
              int ldo, long sO)
{
    extern __shared__ char smem[];
    const uint32_t sbase = smem_u32(smem);
    const int tid = threadIdx.x;
    const int wid = tid >> 5;
    const int L = tid & 31;
    const int bm = blockIdx.y * 128;
    const int bn = blockIdx.x * 128;
    const int wm = wid & 1;       // 0..1  (64 rows each)
    const int wn = wid >> 1;      // 0..3  (32 cols each)

    const bf16* pAh = Ah + (long)blockIdx.z * sA + (long)bm * lda;
    const bf16* pAl = Al + (long)blockIdx.z * sA + (long)bm * lda;
    const bf16* pBh = Bh + (long)blockIdx.z * sB + (long)bn * ldb;
    const bf16* pBl = Bl + (long)blockIdx.z * sB + (long)bn * ldb;

    // ldmatrix lane offsets: unswizzled base + row-pure swizzle pattern.
    // Column advance (+kk*32, lc<=16) never carries into row bits (row stride 64).
    const int lr = L & 15;
    const int lc = (L >> 4) * 16;
    uint32_t aoffu[4], apat[4], boffu[2], bpat[2];
    #pragma unroll
    for (int mt = 0; mt < 4; mt++) {
        const uint32_t off = (uint32_t)((wm * 64 + mt * 16 + lr) * 64 + lc);
        aoffu[mt] = off;
        apat[mt] = (off >> 3) & 0x30;
    }
    #pragma unroll
    for (int ng = 0; ng < 2; ng++) {
        const uint32_t off = (uint32_t)((wn * 32 + ng * 16 + lr) * 64 + lc);
        boffu[ng] = off;
        bpat[ng] = (off >> 3) & 0x30;
    }

    float acc[4][4][4];
    #pragma unroll
    for (int mt = 0; mt < 4; mt++)
        #pragma unroll
        for (int nt = 0; nt < 4; nt++)
            #pragma unroll
            for (int r = 0; r < 4; r++)
                acc[mt][nt][r] = 0.0f;

    const int nchunk = K / 32;

    // prologue: stage 0
    load_tile(sbase + 0 * TILE_B, pAh, lda, tid);
    load_tile(sbase + 1 * TILE_B, pAl, lda, tid);
    load_tile(sbase + 2 * TILE_B, pBh, ldb, tid);
    load_tile(sbase + 3 * TILE_B, pBl, ldb, tid);
    asm volatile("cp.async.commit_group;" ::: "memory");

    for (int ck = 0; ck < nchunk; ck++) {
        const int buf = ck & 1;
        if (ck + 1 < nchunk) {
            const int k0 = (ck + 1) * 32;
            const uint32_t db = sbase + (buf ^ 1) * STAGE_B;
            load_tile(db + 0 * TILE_B, pAh + k0, lda, tid);
            load_tile(db + 1 * TILE_B, pAl + k0, lda, tid);
            load_tile(db + 2 * TILE_B, pBh + k0, ldb, tid);
            load_tile(db + 3 * TILE_B, pBl + k0, ldb, tid);
            asm volatile("cp.async.commit_group;" ::: "memory");
            asm volatile("cp.async.wait_group 1;" ::: "memory");
        } else {
            asm volatile("cp.async.wait_group 0;" ::: "memory");
        }
        __syncthreads();

        const uint32_t cb = sbase + buf * STAGE_B;
        #pragma unroll
        for (int kk = 0; kk < 2; kk++) {
            uint32_t bh[2][4], bl[2][4];
            #pragma unroll
            for (int ng = 0; ng < 2; ng++) {
                const uint32_t sw = (boffu[ng] + kk * 32) ^ bpat[ng];
                LDSM4(bh[ng], cb + 2 * TILE_B + sw);
                LDSM4(bl[ng], cb + 3 * TILE_B + sw);
            }
            #pragma unroll
            for (int mt = 0; mt < 4; mt++) {
                uint32_t ah[4], al[4];
                const uint32_t sw = (aoffu[mt] + kk * 32) ^ apat[mt];
                LDSM4(ah, cb + 0 * TILE_B + sw);
                LDSM4(al, cb + 1 * TILE_B + sw);
                #pragma unroll
                for (int nt = 0; nt < 4; nt++) {
                    const uint32_t bh0 = bh[nt >> 1][nt & 1];
                    const uint32_t bh1 = bh[nt >> 1][(nt & 1) + 2];
                    const uint32_t bl0 = bl[nt >> 1][nt & 1];
                    const uint32_t bl1 = bl[nt >> 1][(nt & 1) + 2];
                    MMA16816(acc[mt][nt], ah, bh0, bh1);
                    MMA16816(acc[mt][nt], ah, bl0, bl1);
                    MMA16816(acc[mt][nt], al, bh0, bh1);
                }
            }
        }
        __syncthreads();
    }

    // epilogue
    const int r0 = bm + wm * 64 + (L >> 2);
    const int c0 = bn + wn * 32 + (L & 3) * 2;
    #pragma unroll
    for (int mt = 0; mt < 4; mt++) {
        #pragma unroll
        for (int nt = 0; nt < 4; nt++) {
            const int row = r0 + mt * 16;
            const int col = c0 + nt * 8;
            if (MODE == 1) {
                float* po = outF + (size_t)blockIdx.z * sO;
                float2 v0 = make_float2(acc[mt][nt][0], acc[mt][nt][1]);
                float2 v1 = make_float2(acc[mt][nt][2], acc[mt][nt][3]);
                *reinterpret_cast<float2*>(po + (size_t)row * ldo + col) = v0;
                *reinterpret_cast<float2*>(po + (size_t)(row + 8) * ldo + col) = v1;
            } else {
                const float b0 = bias[col], b1 = bias[col + 1];
                float x0 = (acc[mt][nt][0] + b0) * scale;
                float x1 = (acc[mt][nt][1] + b1) * scale;
                float x2 = (acc[mt][nt][2] + b0) * scale;
                float x3 = (acc[mt][nt][3] + b1) * scale;
                bf16 h0 = __float2bfloat16(x0), h1 = __float2bfloat16(x1);
                bf16 h2 = __float2bfloat16(x2), h3 = __float2bfloat16(x3);
                bf16 l0 = __float2bfloat16(x0 - __bfloat162float(h0));
                bf16 l1 = __float2bfloat16(x1 - __bfloat162float(h1));
                bf16 l2 = __float2bfloat16(x2 - __bfloat162float(h2));
                bf16 l3 = __float2bfloat16(x3 - __bfloat162float(h3));
                __nv_bfloat162 hh0; hh0.x = h0; hh0.y = h1;
                __nv_bfloat162 hh1; hh1.x = h2; hh1.y = h3;
                __nv_bfloat162 ll0; ll0.x = l0; ll0.y = l1;
                __nv_bfloat162 ll1; ll1.x = l2; ll1.y = l3;
                *reinterpret_cast<__nv_bfloat162*>(outH + (size_t)row * ldo + col) = hh0;
                *reinterpret_cast<__nv_bfloat162*>(outH + (size_t)(row + 8) * ldo + col) = hh1;
                *reinterpret_cast<__nv_bfloat162*>(outL + (size_t)row * ldo + col) = ll0;
                *reinterpret_cast<__nv_bfloat162*>(outL + (size_t)(row + 8) * ldo + col) = ll1;
            }
        }
    }
}

// ---------------- small kernels ----------------
__global__ __launch_bounds__(256) void fsplit(const float* __restrict__ x,
                                              bf16* __restrict__ h, bf16* __restrict__ l)
{
    const int i = (blockIdx.x * 256 + threadIdx.x) * 4;
    float4 v = *reinterpret_cast<const float4*>(x + i);
    bf16 h0 = __float2bfloat16(v.x), h1 = __float2bfloat16(v.y);
    bf16 h2 = __float2bfloat16(v.z), h3 = __float2bfloat16(v.w);
    bf16 l0 = __float2bfloat16(v.x - __bfloat162float(h0));
    bf16 l1 = __float2bfloat16(v.y - __bfloat162float(h1));
    bf16 l2 = __float2bfloat16(v.z - __bfloat162float(h2));
    bf16 l3 = __float2bfloat16(v.w - __bfloat162float(h3));
    __nv_bfloat162 a, b;
    a.x = h0; a.y = h1; b.x = h2; b.y = h3;
    *reinterpret_cast<__nv_bfloat162*>(h + i) = a;
    *reinterpret_cast<__nv_bfloat162*>(h + i + 2) = b;
    a.x = l0; a.y = l1; b.x = l2; b.y = l3;
    *reinterpret_cast<__nv_bfloat162*>(l + i) = a;
    *reinterpret_cast<__nv_bfloat162*>(l + i + 2) = b;
}

// W [K=512, N=512] -> Wt hi/lo [N, K]
__global__ __launch_bounds__(256) void wsplit(const float* __restrict__ W,
                                              bf16* __restrict__ Wth, bf16* __restrict__ Wtl)
{
    __shared__ float t[32][33];
    const int n0 = blockIdx.x * 32, k0 = blockIdx.y * 32;
    const int tx = threadIdx.x & 31, ty = threadIdx.x >> 5;
    #pragma unroll
    for (int i = 0; i < 4; i++) {
        const int r = ty + i * 8;
        t[r][tx] = W[(size_t)(k0 + r) * HD + n0 + tx];
    }
    __syncthreads();
    #pragma unroll
    for (int i = 0; i < 4; i++) {
        const int r = ty + i * 8;          // n
        const float v = t[tx][r];
        bf16 h = __float2bfloat16(v);
        bf16 l = __float2bfloat16(v - __bfloat162float(h));
        const size_t dst = (size_t)(n0 + r) * FT + k0 + tx;
        Wth[dst] = h;
        Wtl[dst] = l;
    }
}

// V hi/lo [B*T, H] -> Vt hi/lo [B][H][T]
__global__ __launch_bounds__(256) void transpose_v(const bf16* __restrict__ Vh,
                                                   const bf16* __restrict__ Vl,
                                                   bf16* __restrict__ Vth, bf16* __restrict__ Vtl)
{
    __shared__ bf16 th[32][33], tl[32][33];
    const int b = blockIdx.z;
    const int h0 = blockIdx.x * 32, s0 = blockIdx.y * 32;
    const int tx = threadIdx.x & 31, ty = threadIdx.x >> 5;
    #pragma unroll
    for (int i = 0; i < 4; i++) {
        const int r = ty + i * 8;
        const size_t src = ((size_t)b * TT + s0 + r) * HD + h0 + tx;
        th[r][tx] = Vh[src];
        tl[r][tx] = Vl[src];
    }
    __syncthreads();
    #pragma unroll
    for (int i = 0; i < 4; i++) {
        const int r = ty + i * 8;          // h
        const size_t dst = ((size_t)b * HD + h0 + r) * TT + s0 + tx;
        Vth[dst] = th[tx][r];
        Vtl[dst] = tl[tx][r];
    }
}

// softmax over rows of 2048; writes P as bf16 hi/lo
__global__ __launch_bounds__(256) void softmax_k(const float* __restrict__ S,
                                                 bf16* __restrict__ Ph, bf16* __restrict__ Pl)
{
    const size_t off = (size_t)blockIdx.x * TT;
    const int tid = threadIdx.x;
    const float* p = S + off + tid * 8;
    float v[8];
    float4 a = *reinterpret_cast<const float4*>(p);
    float4 b = *reinterpret_cast<const float4*>(p + 4);
    v[0] = a.x; v[1] = a.y; v[2] = a.z; v[3] = a.w;
    v[4] = b.x; v[5] = b.y; v[6] = b.z; v[7] = b.w;

    __shared__ float red[8];
    float m = v[0];
    #pragma unroll
    for (int i = 1; i < 8; i++) m = fmaxf(m, v[i]);
    #pragma unroll
    for (int o = 16; o > 0; o >>= 1) m = fmaxf(m, __shfl_xor_sync(0xffffffffu, m, o));
    if ((tid & 31) == 0) red[tid >> 5] = m;
    __syncthreads();
    float M = red[0];
    #pragma unroll
    for (int i = 1; i < 8; i++) M = fmaxf(M, red[i]);
    __syncthreads();

    float s = 0.f;
    #pragma unroll
    for (int i = 0; i < 8; i++) { v[i] = __expf(v[i] - M); s += v[i]; }
    #pragma unroll
    for (int o = 16; o > 0; o >>= 1) s += __shfl_xor_sync(0xffffffffu, s, o);
    if ((tid & 31) == 0) red[tid >> 5] = s;
    __syncthreads();
    float tot = 0.f;
    #pragma unroll
    for (int i = 0; i < 8; i++) tot += red[i];
    const float inv = __fdividef(1.0f, tot);

    bf16* ph = Ph + off + tid * 8;
    bf16* pl = Pl + off + tid * 8;
    #pragma unroll
    for (int i = 0; i < 8; i += 2) {
        float x0 = v[i] * inv, x1 = v[i + 1] * inv;
        bf16 h0 = __float2bfloat16(x0), h1 = __float2bfloat16(x1);
        bf16 l0 = __float2bfloat16(x0 - __bfloat162float(h0));
        bf16 l1 = __float2bfloat16(x1 - __bfloat162float(h1));
        __nv_bfloat162 hh; hh.x = h0; hh.y = h1;
        __nv_bfloat162 ll; ll.x = l0; ll.y = l1;
        *reinterpret_cast<__nv_bfloat162*>(ph + i) = hh;
        *reinterpret_cast<__nv_bfloat162*>(pl + i) = ll;
    }
}

// ---------------- launch ----------------
extern "C" void kernel_launch(void* const* d_in, const int* in_sizes, int n_in,
                              void* d_out, int out_size)
{
    const float* q  = (const float*)d_in[0];
    const float* k  = (const float*)d_in[1];
    const float* v  = (const float*)d_in[2];
    const float* Wq = (const float*)d_in[3];
    const float* bq = (const float*)d_in[4];
    const float* Wk = (const float*)d_in[5];
    const float* bk = (const float*)d_in[6];
    const float* Wv = (const float*)d_in[7];
    const float* bv = (const float*)d_in[8];
    float* out = (float*)d_out;

    bf16 *qh, *ql, *kh, *kl, *vh, *vl;
    bf16 *wqh, *wql, *wkh, *wkl, *wvh, *wvl;
    bf16 *Qh, *Ql, *Kh, *Kl, *Vh, *Vl, *Vth, *Vtl, *Ph, *Pl;
    float* S;
    cudaGetSymbolAddress((void**)&qh, g_qh);   cudaGetSymbolAddress((void**)&ql, g_ql);
    cudaGetSymbolAddress((void**)&kh, g_kh);   cudaGetSymbolAddress((void**)&kl, g_kl);
    cudaGetSymbolAddress((void**)&vh, g_vh);   cudaGetSymbolAddress((void**)&vl, g_vl);
    cudaGetSymbolAddress((void**)&wqh, g_Wqh); cudaGetSymbolAddress((void**)&wql, g_Wql);
    cudaGetSymbolAddress((void**)&wkh, g_Wkh); cudaGetSymbolAddress((void**)&wkl, g_Wkl);
    cudaGetSymbolAddress((void**)&wvh, g_Wvh); cudaGetSymbolAddress((void**)&wvl, g_Wvl);
    cudaGetSymbolAddress((void**)&Qh, g_Qh);   cudaGetSymbolAddress((void**)&Ql, g_Ql);
    cudaGetSymbolAddress((void**)&Kh, g_Kh);   cudaGetSymbolAddress((void**)&Kl, g_Kl);
    cudaGetSymbolAddress((void**)&Vh, g_Vh);   cudaGetSymbolAddress((void**)&Vl, g_Vl);
    cudaGetSymbolAddress((void**)&Vth, g_Vth); cudaGetSymbolAddress((void**)&Vtl, g_Vtl);
    cudaGetSymbolAddress((void**)&S, g_S);
    cudaGetSymbolAddress((void**)&Ph, g_Ph);   cudaGetSymbolAddress((void**)&Pl, g_Pl);

    cudaFuncSetAttribute(gemm_mma<0>, cudaFuncAttributeMaxDynamicSharedMemorySize, GEMM_SMEM);
    cudaFuncSetAttribute(gemm_mma<1>, cudaFuncAttributeMaxDynamicSharedMemorySize, GEMM_SMEM);

    // 1) split inputs
    fsplit<<<MTOT * FT / 1024, 256>>>(q, qh, ql);
    fsplit<<<MTOT * FT / 1024, 256>>>(k, kh, kl);
    fsplit<<<MTOT * FT / 1024, 256>>>(v, vh, vl);
    // 2) transpose+split weights
    wsplit<<<dim3(16, 16), 256>>>(Wq, wqh, wql);
    wsplit<<<dim3(16, 16), 256>>>(Wk, wkh, wkl);
    wsplit<<<dim3(16, 16), 256>>>(Wv, wvh, wvl);
    // 3) projections (scale 0.25 folded into Q)
    dim3 gp(HD / 128, MTOT / 128, 1);
    gemm_mma<0><<<gp, 256, GEMM_SMEM>>>(qh, ql, wqh, wql, FT, FT, 0, 0, FT,
                                        bq, 0.25f, nullptr, Qh, Ql, HD, 0);
    gemm_mma<0><<<gp, 256, GEMM_SMEM>>>(kh, kl, wkh, wkl, FT, FT, 0, 0, FT,
                                        bk, 1.0f, nullptr, Kh, Kl, HD, 0);
    gemm_mma<0><<<gp, 256, GEMM_SMEM>>>(vh, vl, wvh, wvl, FT, FT, 0, 0, FT,
                                        bv, 1.0f, nullptr, Vh, Vl, HD, 0);
    // 4) transpose V
    transpose_v<<<dim3(HD / 32, TT / 32, BZ), 256>>>(Vh, Vl, Vth, Vtl);
    // 5) energy S = (0.25 Q) K^T
    dim3 ge(TT / 128, TT / 128, BZ);
    gemm_mma<1><<<ge, 256, GEMM_SMEM>>>(Qh, Ql, Kh, Kl, HD, HD,
                                        (long)TT * HD, (long)TT * HD, HD,
                                        nullptr, 1.0f, S, nullptr, nullptr,
                                        TT, (long)TT * TT);
    // 6) softmax -> P hi/lo
    softmax_k<<<MTOT, 256>>>(S, Ph, Pl);
    // 7) out = P V
    dim3 go(HD / 128, TT / 128, BZ);
    gemm_mma<1><<<go, 256, GEMM_SMEM>>>(Ph, Pl, Vth, Vtl, TT, TT,
                                        (long)TT * TT, (long)HD * TT, TT,
                                        nullptr, 1.0f, out, nullptr, nullptr,
                                        HD, (long)TT * HD);
}